// round 1
// baseline (speedup 1.0000x reference)
#include <cuda_runtime.h>
#include <math.h>

#define B_   2
#define N_   4096
#define C_   256
#define NC_  150
#define T_   4
#define HID_ 1024
#define R_   16384   /* T_*N_ */

/* ---------------- scratch (device globals; no allocation allowed) -------- */
__device__ float g_xf  [B_*T_*N_*C_];    /* (B,T*N,C)                */
__device__ float g_cl  [B_*NC_*R_];      /* (B,nc,T*N)               */
__device__ float g_soft[B_*T_*NC_*N_];   /* (B*T*nc, N)              */
__device__ float g_cen [B_*T_*NC_*C_];   /* (B*T*nc, C)              */
__device__ float g_cin [B_*NC_*C_];
__device__ float g_k   [B_*NC_*C_];
__device__ float g_v   [B_*NC_*C_];
__device__ float g_q   [B_*N_*C_];
__device__ float g_attn[B_*N_*C_];
__device__ float g_tmp [B_*N_*C_];       /* proj out / fc2 out       */
__device__ float g_out1[B_*N_*C_];
__device__ float g_h1  [B_*N_*HID_];
__device__ float g_hg  [B_*N_*HID_];

/* ---------------- helpers ------------------------------------------------ */
__device__ __forceinline__ float blockSum256(float v, float* sh) {
    #pragma unroll
    for (int o = 16; o; o >>= 1) v += __shfl_xor_sync(0xffffffffu, v, o);
    if ((threadIdx.x & 31) == 0) sh[threadIdx.x >> 5] = v;
    __syncthreads();
    float r = sh[0]+sh[1]+sh[2]+sh[3]+sh[4]+sh[5]+sh[6]+sh[7];
    __syncthreads();
    return r;
}

/* ---------------- xf = concat(mem, x) ------------------------------------ */
__global__ void copy_xf_kernel(const float* __restrict__ x,
                               const float* __restrict__ mem,
                               float* __restrict__ xf) {
    long long i = (long long)blockIdx.x * 256 + threadIdx.x;  /* < 2^23 */
    int b  = (int)(i >> 22);
    int rem = (int)(i & 4194303);
    int tt = rem >> 20;
    int rc = rem & 1048575;
    float v;
    if (tt < 3) v = mem[((long long)(b*3 + tt) << 20) + rc];
    else        v = x[((long long)b << 20) + rc];
    xf[i] = v;
}

/* ---------------- generic register-tiled GEMM  C = alpha*(A·op(W) + bias) -
 * A:(M,K) row-major.  transW=0: W:(N,K) (NT).  transW=1: W:(K,N) (NN).
 * C[m,n] stored at C[m*crs + n*ccs].  batched over blockIdx.z.             */
__global__ void gemm_tile(int M, int N, int K,
                          const float* __restrict__ A, int lda, long long bsA,
                          const float* __restrict__ W, int ldw, long long bsW, int transW,
                          float* __restrict__ C, long long crs, long long ccs, long long bsC,
                          const float* __restrict__ bias, float alpha) {
    int bt = blockIdx.z;
    A += (long long)bt * bsA;  W += (long long)bt * bsW;  C += (long long)bt * bsC;
    int m0 = blockIdx.x * 128, n0 = blockIdx.y * 64;
    __shared__ float As[16][129];
    __shared__ float Ws[16][65];
    int tid = threadIdx.x;
    int tm = tid >> 4, tn = tid & 15;
    float acc[8][4];
    #pragma unroll
    for (int i = 0; i < 8; i++)
        #pragma unroll
        for (int j = 0; j < 4; j++) acc[i][j] = 0.f;

    for (int k0 = 0; k0 < K; k0 += 16) {
        #pragma unroll
        for (int i = tid; i < 16*128; i += 256) {
            int kk = i & 15, mm = i >> 4;
            int m = m0 + mm, k = k0 + kk;
            As[kk][mm] = (m < M && k < K) ? A[(long long)m * lda + k] : 0.f;
        }
        if (!transW) {
            #pragma unroll
            for (int i = tid; i < 16*64; i += 256) {
                int kk = i & 15, nn = i >> 4;
                int n = n0 + nn, k = k0 + kk;
                Ws[kk][nn] = (n < N && k < K) ? W[(long long)n * ldw + k] : 0.f;
            }
        } else {
            #pragma unroll
            for (int i = tid; i < 16*64; i += 256) {
                int nn = i & 63, kk = i >> 6;
                int n = n0 + nn, k = k0 + kk;
                Ws[kk][nn] = (n < N && k < K) ? W[(long long)k * ldw + n] : 0.f;
            }
        }
        __syncthreads();
        #pragma unroll
        for (int kk = 0; kk < 16; kk++) {
            float a[8], w[4];
            #pragma unroll
            for (int i = 0; i < 8; i++) a[i] = As[kk][tm + i*16];
            #pragma unroll
            for (int j = 0; j < 4; j++) w[j] = Ws[kk][tn + j*16];
            #pragma unroll
            for (int i = 0; i < 8; i++)
                #pragma unroll
                for (int j = 0; j < 4; j++) acc[i][j] += a[i] * w[j];
        }
        __syncthreads();
    }
    #pragma unroll
    for (int i = 0; i < 8; i++) {
        int m = m0 + tm + i*16;
        if (m >= M) continue;
        #pragma unroll
        for (int j = 0; j < 4; j++) {
            int n = n0 + tn + j*16;
            if (n >= N) continue;
            float v = acc[i][j];
            if (bias) v += bias[n];
            C[(long long)m * crs + (long long)n * ccs] = v * alpha;
        }
    }
}

/* ---------------- fused prompt/tdt cluster transform --------------------- */
__global__ void cluster_kernel(const float* __restrict__ z, const float* __restrict__ cl,
                               const float* __restrict__ p1, const float* __restrict__ t1,
                               const float* __restrict__ p2, const float* __restrict__ t2,
                               float* __restrict__ out2, float* __restrict__ out3) {
    const int b  = blockIdx.y;
    const int r0 = blockIdx.x * 16;
    __shared__ float zs[NC_][16];
    __shared__ float cs[NC_][16];
    __shared__ float ov[NC_][16];
    __shared__ float pn[2];
    __shared__ float rsc[2][16];
    int tid = threadIdx.x;
    long long zb = (long long)b * NC_ * R_;
    for (int i = tid; i < NC_*16; i += 256) {
        int k = i >> 4, rr = i & 15;
        long long off = zb + (long long)k * R_ + r0 + rr;
        zs[k][rr] = z[off];
        cs[k][rr] = cl[off];
    }
    if (tid < 2) {
        const float* p = tid ? p2 : p1;
        float s = 0.f;
        for (int k = 0; k < NC_; k++) s += p[k]*p[k];
        pn[tid] = 1.0f / fmaxf(sqrtf(s), 1e-12f);
    }
    __syncthreads();
    {
        int rr = tid >> 4, l = tid & 15;
        float szz=0.f, szp=0.f, scc=0.f, scp=0.f;
        for (int k = l; k < NC_; k += 16) {
            float zv = zs[k][rr], cv = cs[k][rr];
            szz += zv*zv; szp += zv*p1[k];
            scc += cv*cv; scp += cv*p2[k];
        }
        #pragma unroll
        for (int o = 8; o; o >>= 1) {
            szz += __shfl_down_sync(0xffffffffu, szz, o, 16);
            szp += __shfl_down_sync(0xffffffffu, szp, o, 16);
            scc += __shfl_down_sync(0xffffffffu, scc, o, 16);
            scp += __shfl_down_sync(0xffffffffu, scp, o, 16);
        }
        if (l == 0) {
            float cz = szp * pn[0] / fmaxf(sqrtf(szz), 1e-12f);
            rsc[0][rr] = fminf(fmaxf(cz, 0.f), 1.f);
            float cc = scp * pn[1] / fmaxf(sqrtf(scc), 1e-12f);
            rsc[1][rr] = fminf(fmaxf(cc, 0.f), 1.f);
        }
    }
    __syncthreads();
    for (int i = tid; i < NC_*16; i += 256) {
        int k = i >> 4, rr = i & 15;
        zs[k][rr] *= rsc[0][rr];
        cs[k][rr] *= rsc[1][rr];
    }
    __syncthreads();
    if (tid < NC_) {
        int kp = tid;
        float acc[16];
        #pragma unroll
        for (int r = 0; r < 16; r++) acc[r] = 0.f;
        for (int k = 0; k < NC_; k++) {
            float t1v = t1[k*NC_ + kp], t2v = t2[k*NC_ + kp];
            const float4* z4 = reinterpret_cast<const float4*>(&zs[k][0]);
            const float4* c4 = reinterpret_cast<const float4*>(&cs[k][0]);
            #pragma unroll
            for (int u = 0; u < 4; u++) {
                float4 zf = z4[u], cf = c4[u];
                acc[u*4+0] += zf.x*t1v + cf.x*t2v;
                acc[u*4+1] += zf.y*t1v + cf.y*t2v;
                acc[u*4+2] += zf.z*t1v + cf.z*t2v;
                acc[u*4+3] += zf.w*t1v + cf.w*t2v;
            }
        }
        #pragma unroll
        for (int r = 0; r < 16; r++) ov[kp][r] = 0.5f * acc[r];
    }
    __syncthreads();
    for (int i = tid; i < NC_*16; i += 256) {
        int kp = i >> 4, rr = i & 15;
        int r = r0 + rr;
        float v = ov[kp][rr];
        out2[zb + (long long)kp * R_ + r] = v;
        int tt = r >> 12, n = r & 4095;
        out3[(((long long)(b*4 + tt)) * NC_ + kp) * 4096 + n] = v;
    }
}

/* ---------------- row softmax over N=4096 -------------------------------- */
__global__ void softmax_rows(const float* __restrict__ src, float* __restrict__ dst) {
    long long row = blockIdx.x;
    const float* s = src + row * N_;
    float* d = dst + row * N_;
    __shared__ float sh[8];
    int tid = threadIdx.x;
    float mx = -1e30f;
    for (int i = tid; i < N_; i += 256) mx = fmaxf(mx, s[i]);
    #pragma unroll
    for (int o = 16; o; o >>= 1) mx = fmaxf(mx, __shfl_xor_sync(0xffffffffu, mx, o));
    if ((tid & 31) == 0) sh[tid >> 5] = mx;
    __syncthreads();
    mx = fmaxf(fmaxf(fmaxf(sh[0],sh[1]),fmaxf(sh[2],sh[3])),
               fmaxf(fmaxf(sh[4],sh[5]),fmaxf(sh[6],sh[7])));
    __syncthreads();
    float sum = 0.f;
    for (int i = tid; i < N_; i += 256) sum += expf(s[i] - mx);
    sum = blockSum256(sum, sh);
    float inv = 1.0f / sum;
    for (int i = tid; i < N_; i += 256) d[i] = expf(s[i] - mx) * inv;
}

/* ---------------- gate + LayerNorm --------------------------------------- */
__global__ void gate_ln_kernel(const float* __restrict__ cen,
                               const float* __restrict__ nw, const float* __restrict__ nb,
                               const float* __restrict__ salpha, const float* __restrict__ sbeta,
                               float* __restrict__ cin_out) {
    int k = blockIdx.x, b = blockIdx.y, c = threadIdx.x;
    __shared__ float sh[8];
    float pv[4];
    #pragma unroll
    for (int t = 0; t < 4; t++)
        pv[t] = cen[(((long long)b*4 + t) * NC_ + k) * C_ + c];
    float last = pv[3];
    float ll = blockSum256(last*last, sh);
    float cin = last;
    float alpha = salpha[0], beta = sbeta[0];
    for (int t = 0; t < 3; t++) {
        float dt = blockSum256(last * pv[t], sh);
        float pp = blockSum256(pv[t] * pv[t], sh);
        float denom = fmaxf(sqrtf(ll) * sqrtf(pp), 1e-8f);
        float gate = 1.0f / (1.0f + expf(-(beta + alpha * (dt / denom))));
        cin += gate * pv[t];
    }
    float m  = blockSum256(cin, sh) * (1.0f / C_);
    float dv = cin - m;
    float var = blockSum256(dv*dv, sh) * (1.0f / C_);
    cin_out[((long long)b*NC_ + k) * C_ + c] = dv * rsqrtf(var + 1e-5f) * nw[c] + nb[c];
}

/* ---------------- K/V projections ---------------------------------------- */
__global__ void kv_kernel(const float* __restrict__ cin,
                          const float* __restrict__ kw, const float* __restrict__ kb,
                          const float* __restrict__ vw, const float* __restrict__ vb,
                          float* __restrict__ ko, float* __restrict__ vo) {
    int row = blockIdx.x, c = threadIdx.x;
    __shared__ float ci[C_];
    ci[c] = cin[(long long)row * C_ + c];
    __syncthreads();
    float ka = kb[c], va = vb[c];
    const float* kwr = kw + (long long)c * C_;
    const float* vwr = vw + (long long)c * C_;
    #pragma unroll 4
    for (int j = 0; j < C_; j++) {
        float cv = ci[j];
        ka += cv * kwr[j];
        va += cv * vwr[j];
    }
    ko[(long long)row * C_ + c] = ka;
    vo[(long long)row * C_ + c] = va;
}

/* ---------------- fused attention (nc=150, 8 heads, 4 queries/block) ----- */
__global__ void attn_kernel(const float* __restrict__ q, const float* __restrict__ ks,
                            const float* __restrict__ vs, float* __restrict__ o) {
    const int b = blockIdx.y;
    const int n0 = blockIdx.x * 4;
    __shared__ float qs[4][C_];
    __shared__ float P[8][4][152];
    int tid = threadIdx.x;
    for (int i = tid; i < 4*C_; i += 256)
        qs[i >> 8][i & 255] = q[((long long)b*N_ + n0 + (i >> 8)) * C_ + (i & 255)];
    __syncthreads();
    int h = tid >> 5, lane = tid & 31;
    float lg[4][5];
    #pragma unroll
    for (int g = 0; g < 4; g++)
        #pragma unroll
        for (int s = 0; s < 5; s++) lg[g][s] = -1e30f;
    #pragma unroll
    for (int s = 0; s < 5; s++) {
        int idx = lane + s*32;
        if (idx < NC_) {
            const float4* kp = reinterpret_cast<const float4*>(ks + ((long long)b*NC_ + idx)*C_ + h*32);
            float4 kk[8];
            #pragma unroll
            for (int u = 0; u < 8; u++) kk[u] = kp[u];
            #pragma unroll
            for (int g = 0; g < 4; g++) {
                const float* qb = &qs[g][h*32];
                float d = 0.f;
                #pragma unroll
                for (int u = 0; u < 8; u++)
                    d += kk[u].x*qb[u*4] + kk[u].y*qb[u*4+1] + kk[u].z*qb[u*4+2] + kk[u].w*qb[u*4+3];
                lg[g][s] = d;
            }
        }
    }
    float invg[4];
    #pragma unroll
    for (int g = 0; g < 4; g++) {
        float mx = -1e30f;
        #pragma unroll
        for (int s = 0; s < 5; s++) mx = fmaxf(mx, lg[g][s]);
        #pragma unroll
        for (int o2 = 16; o2; o2 >>= 1) mx = fmaxf(mx, __shfl_xor_sync(0xffffffffu, mx, o2));
        float sum = 0.f;
        #pragma unroll
        for (int s = 0; s < 5; s++) {
            int idx = lane + s*32;
            if (idx < NC_) {
                float e = expf(lg[g][s] - mx);
                P[h][g][idx] = e;
                sum += e;
            }
        }
        #pragma unroll
        for (int o2 = 16; o2; o2 >>= 1) sum += __shfl_xor_sync(0xffffffffu, sum, o2);
        invg[g] = 1.0f / sum;
    }
    __syncwarp();
    float og[4] = {0.f, 0.f, 0.f, 0.f};
    for (int j = 0; j < NC_; j++) {
        float vv = vs[((long long)b*NC_ + j) * C_ + h*32 + lane];
        #pragma unroll
        for (int g = 0; g < 4; g++) og[g] += P[h][g][j] * vv;
    }
    #pragma unroll
    for (int g = 0; g < 4; g++)
        o[((long long)b*N_ + n0 + g) * C_ + h*32 + lane] = og[g] * invg[g];
}

/* ---------------- depthwise 3x3 conv + exact GELU ------------------------ */
__global__ void conv_gelu_kernel(const float* __restrict__ h,
                                 const float* __restrict__ dww, const float* __restrict__ dwb,
                                 float* __restrict__ out) {
    int ch = blockIdx.x * 256 + threadIdx.x;
    int y  = blockIdx.y;
    int bz = blockIdx.z;
    int b = bz >> 6, xw = bz & 63;
    float acc = dwb[ch];
    #pragma unroll
    for (int dy = 0; dy < 3; dy++) {
        int yy = y + dy - 1;
        if (yy < 0 || yy > 63) continue;
        #pragma unroll
        for (int dx = 0; dx < 3; dx++) {
            int xx = xw + dx - 1;
            if (xx < 0 || xx > 63) continue;
            acc += h[(((long long)b*N_) + (yy*64 + xx)) * HID_ + ch] * dww[ch*9 + dy*3 + dx];
        }
    }
    float gg = 0.5f * acc * (1.0f + erff(acc * 0.7071067811865475f));
    out[(((long long)b*N_) + (y*64 + xw)) * HID_ + ch] = gg;
}

/* ---------------- residual + LayerNorm ----------------------------------- */
__global__ void add_ln_kernel(const float* __restrict__ res, const float* __restrict__ val,
                              const float* __restrict__ nw, const float* __restrict__ nb,
                              float* __restrict__ dst) {
    long long row = blockIdx.x;
    int c = threadIdx.x;
    __shared__ float sh[8];
    float v = val[row * C_ + c];
    float m = blockSum256(v, sh) * (1.0f / C_);
    float d = v - m;
    float var = blockSum256(d*d, sh) * (1.0f / C_);
    dst[row * C_ + c] = res[row * C_ + c] + d * rsqrtf(var + 1e-5f) * nw[c] + nb[c];
}

/* ---------------- host launch -------------------------------------------- */
static float* symaddr(const void* sym) {
    void* p = nullptr;
    cudaGetSymbolAddress(&p, sym);
    return (float*)p;
}

extern "C" void kernel_launch(void* const* d_in, const int* in_sizes, int n_in,
                              void* d_out, int out_size) {
    const float* x    = (const float*)d_in[0];
    const float* z    = (const float*)d_in[1];
    const float* mem  = (const float*)d_in[2];
    const float* cw   = (const float*)d_in[3];
    const float* p1   = (const float*)d_in[4];
    const float* t1   = (const float*)d_in[5];
    const float* p2   = (const float*)d_in[6];
    const float* t2   = (const float*)d_in[7];
    const float* sal  = (const float*)d_in[8];
    const float* sbe  = (const float*)d_in[9];
    const float* qw   = (const float*)d_in[10];
    const float* qb   = (const float*)d_in[11];
    const float* kw   = (const float*)d_in[12];
    const float* kb   = (const float*)d_in[13];
    const float* vw   = (const float*)d_in[14];
    const float* vb   = (const float*)d_in[15];
    const float* pw   = (const float*)d_in[16];
    const float* pb   = (const float*)d_in[17];
    const float* nw   = (const float*)d_in[18];
    const float* nb   = (const float*)d_in[19];
    const float* f1w  = (const float*)d_in[20];
    const float* f1b  = (const float*)d_in[21];
    const float* dww  = (const float*)d_in[22];
    const float* dwb  = (const float*)d_in[23];
    const float* f2w  = (const float*)d_in[24];
    const float* f2b  = (const float*)d_in[25];

    float* out_main = (float*)d_out;                     /* (B,N,C)        */
    float* out_cxz  = out_main + (long long)B_*N_*C_;    /* (B,nc,T*N)     */
    float* out_asn  = out_cxz  + (long long)B_*NC_*R_;   /* (B,T,nc,N)     */

    float* xf   = symaddr(g_xf);
    float* cl   = symaddr(g_cl);
    float* soft = symaddr(g_soft);
    float* cen  = symaddr(g_cen);
    float* cin  = symaddr(g_cin);
    float* ksc  = symaddr(g_k);
    float* vsc  = symaddr(g_v);
    float* qsc  = symaddr(g_q);
    float* atn  = symaddr(g_attn);
    float* tmp  = symaddr(g_tmp);
    float* out1 = symaddr(g_out1);
    float* h1   = symaddr(g_h1);
    float* hg   = symaddr(g_hg);

    /* 1. xf = concat(mem, x) : (B, T*N, C) */
    copy_xf_kernel<<<32768, 256>>>(x, mem, xf);

    /* 2. cl[b,k,r] = xf[b,r,:] . cw[k,:]  (transposed store) */
    gemm_tile<<<dim3(128, 3, 2), 256>>>(R_, NC_, C_,
        xf, C_, (long long)R_*C_, cw, C_, 0, 0,
        cl, 1, R_, (long long)NC_*R_, nullptr, 1.0f);

    /* 3. prompt/tdt transform -> cluster_x_z (out2) + assigned (out3) */
    cluster_kernel<<<dim3(R_/16, B_), 256>>>(z, cl, p1, t1, p2, t2, out_cxz, out_asn);

    /* 4. softmax over N per (b,t,k) row */
    softmax_rows<<<B_*T_*NC_, 256>>>(out_asn, soft);

    /* 5. cen[bt,k,c] = soft[bt,k,:] @ xf[bt,:,c]  (NN) */
    gemm_tile<<<dim3(2, 4, 8), 256>>>(NC_, C_, N_,
        soft, N_, (long long)NC_*N_, xf, C_, (long long)N_*C_, 1,
        cen, C_, 1, (long long)NC_*C_, nullptr, 1.0f);

    /* 6. gate + LN -> C_in */
    gate_ln_kernel<<<dim3(NC_, B_), 256>>>(cen, nw, nb, sal, sbe, cin);

    /* 7. k,v projections */
    kv_kernel<<<B_*NC_, 256>>>(cin, kw, kb, vw, vb, ksc, vsc);

    /* 8. q = (x @ qw^T + qb) / sqrt(32) */
    gemm_tile<<<dim3(64, 4, 1), 256>>>(B_*N_, C_, C_,
        x, C_, 0, qw, C_, 0, 0,
        qsc, C_, 1, 0, qb, 0.17677669529663687f);

    /* 9. attention -> concat-head output */
    attn_kernel<<<dim3(N_/4, B_), 256>>>(qsc, ksc, vsc, atn);

    /* 10. proj */
    gemm_tile<<<dim3(64, 4, 1), 256>>>(B_*N_, C_, C_,
        atn, C_, 0, pw, C_, 0, 0,
        tmp, C_, 1, 0, pb, 1.0f);

    /* 11. out1 = x + LN(proj) */
    add_ln_kernel<<<B_*N_, 256>>>(x, tmp, nw, nb, out1);

    /* 12. fc1 */
    gemm_tile<<<dim3(64, 16, 1), 256>>>(B_*N_, HID_, C_,
        out1, C_, 0, f1w, C_, 0, 0,
        h1, HID_, 1, 0, f1b, 1.0f);

    /* 13. depthwise conv + GELU */
    conv_gelu_kernel<<<dim3(HID_/256, 64, 64*B_), 256>>>(h1, dww, dwb, hg);

    /* 14. fc2 */
    gemm_tile<<<dim3(64, 4, 1), 256>>>(B_*N_, C_, HID_,
        hg, HID_, 0, f2w, HID_, 0, 0,
        tmp, C_, 1, 0, f2b, 1.0f);

    /* 15. out = out1 + LN(fc2) */
    add_ln_kernel<<<B_*N_, 256>>>(out1, tmp, nw, nb, out_main);
}

// round 2
// speedup vs baseline: 1.6043x; 1.6043x over previous
#include <cuda_runtime.h>
#include <math.h>

#define B_   2
#define N_   4096
#define C_   256
#define NC_  150
#define T_   4
#define HID_ 1024
#define R_   16384   /* T_*N_ */
#define KC_  304     /* padded 2*NC_ */

/* ---------------- scratch (device globals) ------------------------------- */
__device__ float g_xf  [B_*T_*N_*C_];    /* (B,T*N,C)            */
__device__ float g_cl  [B_*R_*NC_];      /* (B,R,nc) row-major   */
__device__ float g_S   [B_*KC_*R_];      /* (B,304,R) K-major    */
__device__ float g_tcat[NC_*KC_];        /* (150,304)            */
__device__ float g_soft[B_*T_*NC_*N_];   /* (bt,k,N)             */
__device__ float g_cen [B_*T_*NC_*C_];
__device__ float g_cin [B_*NC_*C_];
__device__ float g_k   [B_*NC_*C_];
__device__ float g_v   [B_*NC_*C_];
__device__ float g_q   [B_*N_*C_];
__device__ float g_attn[B_*N_*C_];
__device__ float g_tmp [B_*N_*C_];
__device__ float g_out1[B_*N_*C_];
__device__ float g_h1  [B_*N_*HID_];
__device__ float g_hg  [B_*N_*HID_];

/* ---------------- helpers ------------------------------------------------ */
__device__ __forceinline__ float blockSum256(float v, float* sh) {
    #pragma unroll
    for (int o = 16; o; o >>= 1) v += __shfl_xor_sync(0xffffffffu, v, o);
    if ((threadIdx.x & 31) == 0) sh[threadIdx.x >> 5] = v;
    __syncthreads();
    float r = sh[0]+sh[1]+sh[2]+sh[3]+sh[4]+sh[5]+sh[6]+sh[7];
    __syncthreads();
    return r;
}

__global__ void zero_kernel(float* p, int n) {
    int i = blockIdx.x * 256 + threadIdx.x;
    if (i < n) p[i] = 0.f;
}

/* ---------------- xf = concat(mem, x) ------------------------------------ */
__global__ void copy_xf_kernel(const float* __restrict__ x,
                               const float* __restrict__ mem,
                               float* __restrict__ xf) {
    long long i = (long long)blockIdx.x * 256 + threadIdx.x;
    int b  = (int)(i >> 22);
    int rem = (int)(i & 4194303);
    int tt = rem >> 20;
    int rc = rem & 1048575;
    float v;
    if (tt < 3) v = mem[((long long)(b*3 + tt) << 20) + rc];
    else        v = x[((long long)b << 20) + rc];
    xf[i] = v;
}

/* ---------------- templated SGEMM  C = alpha*(A·op(W) + bias) -------------
 * A:(M,K) row-major. transW=0: W:(N,K). transW=1: W:(K,N).
 * C[m,n] at C[m*crs+n*ccs]; batched over bt=z/ksplit; splitK via atomicAdd. */
template<int BM, int BN, int TM, int TN>
__global__ void gemm_t(int M, int N, int K,
                       const float* __restrict__ A, int lda, long long bsA,
                       const float* __restrict__ W, int ldw, long long bsW, int transW,
                       float* __restrict__ Cp, long long crs, long long ccs, long long bsC,
                       const float* __restrict__ bias, float alpha, int ksplit) {
    constexpr int BK = 8;
    constexpr int TX = BN / TN, TY = BM / TM, NT = TX * TY;
    __shared__ float As[BK][BM + 4];
    __shared__ float Ws[BK][BN + 4];
    int zz = blockIdx.z;
    int bt = zz / ksplit, ks = zz - bt * ksplit;
    A  += (long long)bt * bsA;
    W  += (long long)bt * bsW;
    Cp += (long long)bt * bsC;
    int Kc = (K + ksplit - 1) / ksplit;
    int kbeg = ks * Kc;
    int kend = min(K, kbeg + Kc);
    int m0 = blockIdx.x * BM, n0 = blockIdx.y * BN;
    int tid = threadIdx.x;
    int tx = tid % TX, ty = tid / TX;
    float acc[TM][TN];
    #pragma unroll
    for (int i = 0; i < TM; i++)
        #pragma unroll
        for (int j = 0; j < TN; j++) acc[i][j] = 0.f;

    for (int k0 = kbeg; k0 < kend; k0 += BK) {
        #pragma unroll
        for (int p = 0; p < BK * BM / NT; p++) {
            int idx = tid + p * NT;
            int kk = idx % BK, mm = idx / BK;
            int m = m0 + mm, k = k0 + kk;
            As[kk][mm] = (m < M && k < kend) ? A[(long long)m * lda + k] : 0.f;
        }
        if (!transW) {
            #pragma unroll
            for (int p = 0; p < BK * BN / NT; p++) {
                int idx = tid + p * NT;
                int kk = idx % BK, nn = idx / BK;
                int n = n0 + nn, k = k0 + kk;
                Ws[kk][nn] = (n < N && k < kend) ? W[(long long)n * ldw + k] : 0.f;
            }
        } else {
            #pragma unroll
            for (int p = 0; p < BK * BN / NT; p++) {
                int idx = tid + p * NT;
                int nn = idx % BN, kk = idx / BN;
                int n = n0 + nn, k = k0 + kk;
                Ws[kk][nn] = (n < N && k < kend) ? W[(long long)k * ldw + n] : 0.f;
            }
        }
        __syncthreads();
        #pragma unroll
        for (int kk = 0; kk < BK; kk++) {
            float a[TM], w[TN];
            #pragma unroll
            for (int i = 0; i < TM; i++) a[i] = As[kk][ty * TM + i];
            #pragma unroll
            for (int j = 0; j < TN; j++) w[j] = Ws[kk][tx * TN + j];
            #pragma unroll
            for (int i = 0; i < TM; i++)
                #pragma unroll
                for (int j = 0; j < TN; j++) acc[i][j] += a[i] * w[j];
        }
        __syncthreads();
    }
    #pragma unroll
    for (int i = 0; i < TM; i++) {
        int m = m0 + ty * TM + i;
        if (m >= M) continue;
        #pragma unroll
        for (int j = 0; j < TN; j++) {
            int n = n0 + tx * TN + j;
            if (n >= N) continue;
            float v = acc[i][j];
            if (bias && ks == 0) v += bias[n];
            v *= alpha;
            float* dst = Cp + (long long)m * crs + (long long)n * ccs;
            if (ksplit == 1) *dst = v;
            else atomicAdd(dst, v);
        }
    }
}

/* ---------------- build Tcat^T (150 x 304) -------------------------------- */
__global__ void tcat_kernel(const float* __restrict__ t1, const float* __restrict__ t2,
                            float* __restrict__ tc) {
    int idx = blockIdx.x * 256 + threadIdx.x;
    if (idx >= NC_ * KC_) return;
    int kp = idx / KC_, j = idx % KC_;
    float v = 0.f;
    if (j < NC_)          v = t1[j * NC_ + kp];
    else if (j < 2*NC_)   v = t2[(j - NC_) * NC_ + kp];
    tc[idx] = v;
}

/* ---------------- cosine-gate scaling + concat -> S (B,304,R) ------------- */
__global__ void scale_concat(const float* __restrict__ z, const float* __restrict__ cl,
                             const float* __restrict__ p1, const float* __restrict__ p2,
                             float* __restrict__ S) {
    int b = blockIdx.y;
    int r = blockIdx.x * 256 + threadIdx.x;
    const float* zb  = z  + (long long)b * NC_ * R_ + r;
    const float* clb = cl + ((long long)b * R_ + r) * NC_;
    float zz = 0.f, zp = 0.f, pp1 = 0.f, cc = 0.f, cp = 0.f, pp2 = 0.f;
    for (int j = 0; j < NC_; j++) {
        float pv1 = p1[j], pv2 = p2[j];
        float zv = zb[(long long)j * R_];
        float cv = clb[j];
        zz += zv * zv; zp += zv * pv1; pp1 += pv1 * pv1;
        cc += cv * cv; cp += cv * pv2; pp2 += pv2 * pv2;
    }
    float s1 = zp / fmaxf(sqrtf(zz), 1e-12f) / fmaxf(sqrtf(pp1), 1e-12f);
    s1 = fminf(fmaxf(s1, 0.f), 1.f);
    float s2 = cp / fmaxf(sqrtf(cc), 1e-12f) / fmaxf(sqrtf(pp2), 1e-12f);
    s2 = fminf(fmaxf(s2, 0.f), 1.f);
    float* Sb = S + (long long)b * KC_ * R_ + r;
    for (int j = 0; j < NC_; j++) {
        Sb[(long long)j * R_]          = zb[(long long)j * R_] * s1;
        Sb[(long long)(NC_ + j) * R_]  = clb[j] * s2;
    }
}

/* ---------------- softmax + raw copy (reads cluster_x_z) ------------------ */
__global__ void softmax_rows2(const float* __restrict__ cxz,
                              float* __restrict__ asn, float* __restrict__ soft) {
    int row = blockIdx.x;                 /* b*600 + t*150 + k */
    int b = row / 600; int rem = row - b * 600;
    int t = rem / NC_; int k = rem - t * NC_;
    const float* s = cxz + ((long long)(b * NC_ + k)) * R_ + (long long)t * N_;
    long long drow = ((long long)((b * T_ + t) * NC_ + k)) * N_;
    __shared__ float sh[8];
    int tid = threadIdx.x;
    float mx = -1e30f;
    for (int i = tid; i < N_; i += 256) mx = fmaxf(mx, s[i]);
    #pragma unroll
    for (int o = 16; o; o >>= 1) mx = fmaxf(mx, __shfl_xor_sync(0xffffffffu, mx, o));
    if ((tid & 31) == 0) sh[tid >> 5] = mx;
    __syncthreads();
    mx = fmaxf(fmaxf(fmaxf(sh[0],sh[1]),fmaxf(sh[2],sh[3])),
               fmaxf(fmaxf(sh[4],sh[5]),fmaxf(sh[6],sh[7])));
    __syncthreads();
    float sum = 0.f;
    for (int i = tid; i < N_; i += 256) sum += expf(s[i] - mx);
    sum = blockSum256(sum, sh);
    float inv = 1.0f / sum;
    for (int i = tid; i < N_; i += 256) {
        float v = s[i];
        asn[drow + i]  = v;
        soft[drow + i] = expf(v - mx) * inv;
    }
}

/* ---------------- gate + LayerNorm --------------------------------------- */
__global__ void gate_ln_kernel(const float* __restrict__ cen,
                               const float* __restrict__ nw, const float* __restrict__ nb,
                               const float* __restrict__ salpha, const float* __restrict__ sbeta,
                               float* __restrict__ cin_out) {
    int k = blockIdx.x, b = blockIdx.y, c = threadIdx.x;
    __shared__ float sh[8];
    float pv[4];
    #pragma unroll
    for (int t = 0; t < 4; t++)
        pv[t] = cen[(((long long)b*4 + t) * NC_ + k) * C_ + c];
    float last = pv[3];
    float ll = blockSum256(last*last, sh);
    float cin = last;
    float alpha = salpha[0], beta = sbeta[0];
    for (int t = 0; t < 3; t++) {
        float dt = blockSum256(last * pv[t], sh);
        float pp = blockSum256(pv[t] * pv[t], sh);
        float denom = fmaxf(sqrtf(ll) * sqrtf(pp), 1e-8f);
        float gate = 1.0f / (1.0f + expf(-(beta + alpha * (dt / denom))));
        cin += gate * pv[t];
    }
    float m  = blockSum256(cin, sh) * (1.0f / C_);
    float dv = cin - m;
    float var = blockSum256(dv*dv, sh) * (1.0f / C_);
    cin_out[((long long)b*NC_ + k) * C_ + c] = dv * rsqrtf(var + 1e-5f) * nw[c] + nb[c];
}

/* ---------------- K/V projections ---------------------------------------- */
__global__ void kv_kernel(const float* __restrict__ cin,
                          const float* __restrict__ kw, const float* __restrict__ kb,
                          const float* __restrict__ vw, const float* __restrict__ vb,
                          float* __restrict__ ko, float* __restrict__ vo) {
    int row = blockIdx.x, c = threadIdx.x;
    __shared__ float ci[C_];
    ci[c] = cin[(long long)row * C_ + c];
    __syncthreads();
    float ka = kb[c], va = vb[c];
    const float* kwr = kw + (long long)c * C_;
    const float* vwr = vw + (long long)c * C_;
    #pragma unroll 4
    for (int j = 0; j < C_; j++) {
        float cv = ci[j];
        ka += cv * kwr[j];
        va += cv * vwr[j];
    }
    ko[(long long)row * C_ + c] = ka;
    vo[(long long)row * C_ + c] = va;
}

/* ---------------- fused attention (nc=150, 8 heads, 4 queries/block) ----- */
__global__ void attn_kernel(const float* __restrict__ q, const float* __restrict__ ks,
                            const float* __restrict__ vs, float* __restrict__ o) {
    const int b = blockIdx.y;
    const int n0 = blockIdx.x * 4;
    __shared__ float qs[4][C_];
    __shared__ float P[8][4][152];
    int tid = threadIdx.x;
    for (int i = tid; i < 4*C_; i += 256)
        qs[i >> 8][i & 255] = q[((long long)b*N_ + n0 + (i >> 8)) * C_ + (i & 255)];
    __syncthreads();
    int h = tid >> 5, lane = tid & 31;
    float lg[4][5];
    #pragma unroll
    for (int g = 0; g < 4; g++)
        #pragma unroll
        for (int s = 0; s < 5; s++) lg[g][s] = -1e30f;
    #pragma unroll
    for (int s = 0; s < 5; s++) {
        int idx = lane + s*32;
        if (idx < NC_) {
            const float4* kp = reinterpret_cast<const float4*>(ks + ((long long)b*NC_ + idx)*C_ + h*32);
            float4 kk[8];
            #pragma unroll
            for (int u = 0; u < 8; u++) kk[u] = kp[u];
            #pragma unroll
            for (int g = 0; g < 4; g++) {
                const float* qb = &qs[g][h*32];
                float d = 0.f;
                #pragma unroll
                for (int u = 0; u < 8; u++)
                    d += kk[u].x*qb[u*4] + kk[u].y*qb[u*4+1] + kk[u].z*qb[u*4+2] + kk[u].w*qb[u*4+3];
                lg[g][s] = d;
            }
        }
    }
    float invg[4];
    #pragma unroll
    for (int g = 0; g < 4; g++) {
        float mx = -1e30f;
        #pragma unroll
        for (int s = 0; s < 5; s++) mx = fmaxf(mx, lg[g][s]);
        #pragma unroll
        for (int o2 = 16; o2; o2 >>= 1) mx = fmaxf(mx, __shfl_xor_sync(0xffffffffu, mx, o2));
        float sum = 0.f;
        #pragma unroll
        for (int s = 0; s < 5; s++) {
            int idx = lane + s*32;
            if (idx < NC_) {
                float e = expf(lg[g][s] - mx);
                P[h][g][idx] = e;
                sum += e;
            }
        }
        #pragma unroll
        for (int o2 = 16; o2; o2 >>= 1) sum += __shfl_xor_sync(0xffffffffu, sum, o2);
        invg[g] = 1.0f / sum;
    }
    __syncwarp();
    float og[4] = {0.f, 0.f, 0.f, 0.f};
    for (int j = 0; j < NC_; j++) {
        float vv = vs[((long long)b*NC_ + j) * C_ + h*32 + lane];
        #pragma unroll
        for (int g = 0; g < 4; g++) og[g] += P[h][g][j] * vv;
    }
    #pragma unroll
    for (int g = 0; g < 4; g++)
        o[((long long)b*N_ + n0 + g) * C_ + h*32 + lane] = og[g] * invg[g];
}

/* ---------------- depthwise 3x3 conv + exact GELU ------------------------ */
__global__ void conv_gelu_kernel(const float* __restrict__ h,
                                 const float* __restrict__ dww, const float* __restrict__ dwb,
                                 float* __restrict__ out) {
    int ch = blockIdx.x * 256 + threadIdx.x;
    int y  = blockIdx.y;
    int bz = blockIdx.z;
    int b = bz >> 6, xw = bz & 63;
    float acc = dwb[ch];
    #pragma unroll
    for (int dy = 0; dy < 3; dy++) {
        int yy = y + dy - 1;
        if (yy < 0 || yy > 63) continue;
        #pragma unroll
        for (int dx = 0; dx < 3; dx++) {
            int xx = xw + dx - 1;
            if (xx < 0 || xx > 63) continue;
            acc += h[(((long long)b*N_) + (yy*64 + xx)) * HID_ + ch] * dww[ch*9 + dy*3 + dx];
        }
    }
    float gg = 0.5f * acc * (1.0f + erff(acc * 0.7071067811865475f));
    out[(((long long)b*N_) + (y*64 + xw)) * HID_ + ch] = gg;
}

/* ---------------- residual + LayerNorm ----------------------------------- */
__global__ void add_ln_kernel(const float* __restrict__ res, const float* __restrict__ val,
                              const float* __restrict__ nw, const float* __restrict__ nb,
                              float* __restrict__ dst) {
    long long row = blockIdx.x;
    int c = threadIdx.x;
    __shared__ float sh[8];
    float v = val[row * C_ + c];
    float m = blockSum256(v, sh) * (1.0f / C_);
    float d = v - m;
    float var = blockSum256(d*d, sh) * (1.0f / C_);
    dst[row * C_ + c] = res[row * C_ + c] + d * rsqrtf(var + 1e-5f) * nw[c] + nb[c];
}

/* ---------------- host launch -------------------------------------------- */
static float* symaddr(const void* sym) {
    void* p = nullptr;
    cudaGetSymbolAddress(&p, sym);
    return (float*)p;
}

extern "C" void kernel_launch(void* const* d_in, const int* in_sizes, int n_in,
                              void* d_out, int out_size) {
    const float* x    = (const float*)d_in[0];
    const float* z    = (const float*)d_in[1];
    const float* mem  = (const float*)d_in[2];
    const float* cw   = (const float*)d_in[3];
    const float* p1   = (const float*)d_in[4];
    const float* t1   = (const float*)d_in[5];
    const float* p2   = (const float*)d_in[6];
    const float* t2   = (const float*)d_in[7];
    const float* sal  = (const float*)d_in[8];
    const float* sbe  = (const float*)d_in[9];
    const float* qw   = (const float*)d_in[10];
    const float* qb   = (const float*)d_in[11];
    const float* kw   = (const float*)d_in[12];
    const float* kb   = (const float*)d_in[13];
    const float* vw   = (const float*)d_in[14];
    const float* vb   = (const float*)d_in[15];
    const float* pw   = (const float*)d_in[16];
    const float* pb   = (const float*)d_in[17];
    const float* nw   = (const float*)d_in[18];
    const float* nb   = (const float*)d_in[19];
    const float* f1w  = (const float*)d_in[20];
    const float* f1b  = (const float*)d_in[21];
    const float* dww  = (const float*)d_in[22];
    const float* dwb  = (const float*)d_in[23];
    const float* f2w  = (const float*)d_in[24];
    const float* f2b  = (const float*)d_in[25];

    float* out_main = (float*)d_out;
    float* out_cxz  = out_main + (long long)B_*N_*C_;
    float* out_asn  = out_cxz  + (long long)B_*NC_*R_;

    float* xf   = symaddr(g_xf);
    float* cl   = symaddr(g_cl);
    float* S    = symaddr(g_S);
    float* tcat = symaddr(g_tcat);
    float* soft = symaddr(g_soft);
    float* cen  = symaddr(g_cen);
    float* cin  = symaddr(g_cin);
    float* ksc  = symaddr(g_k);
    float* vsc  = symaddr(g_v);
    float* qsc  = symaddr(g_q);
    float* atn  = symaddr(g_attn);
    float* tmp  = symaddr(g_tmp);
    float* out1 = symaddr(g_out1);
    float* h1   = symaddr(g_h1);
    float* hg   = symaddr(g_hg);

    /* 1. xf = concat(mem, x) */
    copy_xf_kernel<<<32768, 256>>>(x, mem, xf);

    /* 2. cl[b,r,k] = xf[b,r,:]·cw[k,:]  (M=R, N=150, 128x32 tile) */
    gemm_t<128,32,8,4><<<dim3(R_/128, 5, B_), 128>>>(
        R_, NC_, C_, xf, C_, (long long)R_*C_,
        cw, C_, 0, 0,
        cl, NC_, 1, (long long)R_*NC_, nullptr, 1.0f, 1);

    /* 3. Tcat^T, cosine scales, concat */
    tcat_kernel<<<(NC_*KC_ + 255)/256, 256>>>(t1, t2, tcat);
    scale_concat<<<dim3(R_/256, B_), 256>>>(z, cl, p1, p2, S);

    /* 4. cluster_x_z = 0.5 * Tcat^T @ S   (M=150, N=R, K=300) */
    gemm_t<64,64,4,4><<<dim3(3, R_/64, B_), 256>>>(
        NC_, R_, 2*NC_, tcat, KC_, 0,
        S, R_, (long long)KC_*R_, 1,
        out_cxz, R_, 1, (long long)NC_*R_, nullptr, 0.5f, 1);

    /* 5. softmax + assigned copy */
    softmax_rows2<<<B_*T_*NC_, 256>>>(out_cxz, out_asn, soft);

    /* 6. cen = soft @ xf  (split-K=8, atomic) */
    zero_kernel<<<(B_*T_*NC_*C_ + 255)/256, 256>>>(cen, B_*T_*NC_*C_);
    gemm_t<64,64,4,4><<<dim3(3, 4, B_*T_*8), 256>>>(
        NC_, C_, N_, soft, N_, (long long)NC_*N_,
        xf, C_, (long long)N_*C_, 1,
        cen, C_, 1, (long long)NC_*C_, nullptr, 1.0f, 8);

    /* 7. gate + LN */
    gate_ln_kernel<<<dim3(NC_, B_), 256>>>(cen, nw, nb, sal, sbe, cin);

    /* 8. k,v */
    kv_kernel<<<B_*NC_, 256>>>(cin, kw, kb, vw, vb, ksc, vsc);

    /* 9. q (split-K=2) */
    zero_kernel<<<(B_*N_*C_ + 255)/256, 256>>>(qsc, B_*N_*C_);
    gemm_t<128,128,8,8><<<dim3(64, 2, 2), 256>>>(
        B_*N_, C_, C_, x, C_, 0, qw, C_, 0, 0,
        qsc, C_, 1, 0, qb, 0.17677669529663687f, 2);

    /* 10. attention */
    attn_kernel<<<dim3(N_/4, B_), 256>>>(qsc, ksc, vsc, atn);

    /* 11. proj (split-K=2) */
    zero_kernel<<<(B_*N_*C_ + 255)/256, 256>>>(tmp, B_*N_*C_);
    gemm_t<128,128,8,8><<<dim3(64, 2, 2), 256>>>(
        B_*N_, C_, C_, atn, C_, 0, pw, C_, 0, 0,
        tmp, C_, 1, 0, pb, 1.0f, 2);

    /* 12. out1 = x + LN(proj) */
    add_ln_kernel<<<B_*N_, 256>>>(x, tmp, nw, nb, out1);

    /* 13. fc1 */
    gemm_t<128,128,8,8><<<dim3(64, 8, 1), 256>>>(
        B_*N_, HID_, C_, out1, C_, 0, f1w, C_, 0, 0,
        h1, HID_, 1, 0, f1b, 1.0f, 1);

    /* 14. depthwise conv + GELU */
    conv_gelu_kernel<<<dim3(HID_/256, 64, 64*B_), 256>>>(h1, dww, dwb, hg);

    /* 15. fc2 (split-K=2) */
    zero_kernel<<<(B_*N_*C_ + 255)/256, 256>>>(tmp, B_*N_*C_);
    gemm_t<128,128,8,8><<<dim3(64, 2, 2), 256>>>(
        B_*N_, C_, HID_, hg, HID_, 0, f2w, HID_, 0, 0,
        tmp, C_, 1, 0, f2b, 1.0f, 2);

    /* 16. out = out1 + LN(fc2) */
    add_ln_kernel<<<B_*N_, 256>>>(out1, tmp, nw, nb, out_main);
}